// round 1
// baseline (speedup 1.0000x reference)
#include <cuda_runtime.h>
#include <math.h>

#define B_ROWS 16384
#define N_G    8192
#define D      256
#define MT     64
#define NT     128
#define KC     16

// ---- device scratch (no allocation allowed) ----
__device__ float        d_sums[N_G * D];
__device__ unsigned int d_counts[N_G];
__device__ float        d_rnorm[N_G];

// ---------------------------------------------------------------------------
// K0: per-group: zero sums + counts, compute 1/max(||g||, eps)
// ---------------------------------------------------------------------------
__global__ void __launch_bounds__(256) prep_kernel(const float* __restrict__ gf) {
    int g = blockIdx.x;
    int t = threadIdx.x;            // 256 threads, one per dim
    float v = gf[g * D + t];
    d_sums[g * D + t] = 0.0f;

    float s = v * v;
    #pragma unroll
    for (int o = 16; o; o >>= 1) s += __shfl_xor_sync(0xFFFFFFFFu, s, o);

    __shared__ float red[8];
    if ((t & 31) == 0) red[t >> 5] = s;
    __syncthreads();
    if (t < 8) {
        float r = red[t];
        #pragma unroll
        for (int o = 4; o; o >>= 1) r += __shfl_xor_sync(0xFFu, r, o);
        if (t == 0) {
            float n = sqrtf(r);
            d_rnorm[g] = 1.0f / fmaxf(n, 1e-12f);
            d_counts[g] = 0u;
        }
    }
}

// ---------------------------------------------------------------------------
// K1: fused SGEMM + argmax over groups + segment-sum accumulation
//   grid = B_ROWS/MT blocks, 256 threads each
//   thread (tx,ty): tx = tid&15 owns cols {tx+16j}, ty = tid>>4 owns rows {ty+16i}
// ---------------------------------------------------------------------------
__global__ void __launch_bounds__(256) assign_kernel(const float* __restrict__ x,
                                                     const float* __restrict__ gf) {
    __shared__ float As[KC][MT + 1];    // +1 pad to break STS conflicts
    __shared__ float Bs[KC][NT + 1];
    __shared__ float sbest[MT][16];
    __shared__ int   sidx[MT][16];
    __shared__ int   swin[MT];

    const int tid = threadIdx.x;
    const int tx  = tid & 15;
    const int ty  = tid >> 4;
    const int bm  = blockIdx.x * MT;

    float best[4];
    int   bidx[4];
    #pragma unroll
    for (int i = 0; i < 4; i++) { best[i] = -1e30f; bidx[i] = 0; }

    for (int bn = 0; bn < N_G; bn += NT) {
        float c[4][8];
        #pragma unroll
        for (int i = 0; i < 4; i++)
            #pragma unroll
            for (int j = 0; j < 8; j++) c[i][j] = 0.0f;

        for (int k0 = 0; k0 < D; k0 += KC) {
            // load A tile (transposed): 64 rows x 16 k  -> 256 thr x 1 float4
            {
                int m  = tid >> 2;            // 0..63
                int kq = (tid & 3) << 2;      // 0,4,8,12
                float4 v = *(const float4*)&x[(bm + m) * D + k0 + kq];
                As[kq + 0][m] = v.x; As[kq + 1][m] = v.y;
                As[kq + 2][m] = v.z; As[kq + 3][m] = v.w;
            }
            // load B tile (transposed): 128 rows x 16 k -> 256 thr x 2 float4
            #pragma unroll
            for (int r = 0; r < 2; r++) {
                int id = tid + r * 256;       // 0..511
                int n  = id >> 2;             // 0..127
                int kq = (id & 3) << 2;
                float4 v = *(const float4*)&gf[(bn + n) * D + k0 + kq];
                Bs[kq + 0][n] = v.x; Bs[kq + 1][n] = v.y;
                Bs[kq + 2][n] = v.z; Bs[kq + 3][n] = v.w;
            }
            __syncthreads();

            #pragma unroll
            for (int kk = 0; kk < KC; kk++) {
                float a[4], b[8];
                #pragma unroll
                for (int i = 0; i < 4; i++) a[i] = As[kk][ty + 16 * i];
                #pragma unroll
                for (int j = 0; j < 8; j++) b[j] = Bs[kk][tx + 16 * j];
                #pragma unroll
                for (int i = 0; i < 4; i++)
                    #pragma unroll
                    for (int j = 0; j < 8; j++) c[i][j] = fmaf(a[i], b[j], c[i][j]);
            }
            __syncthreads();
        }

        // scale by group inverse-norm, update running argmax (ascending n order
        // within each (i) slot => strict > keeps the first max index)
        #pragma unroll
        for (int j = 0; j < 8; j++) {
            int n = bn + tx + 16 * j;
            float rn = __ldg(&d_rnorm[n]);
            #pragma unroll
            for (int i = 0; i < 4; i++) {
                float v = c[i][j] * rn;
                if (v > best[i]) { best[i] = v; bidx[i] = n; }
            }
        }
    }

    // block argmax reduction: 16 tx-partials per row
    #pragma unroll
    for (int i = 0; i < 4; i++) {
        sbest[ty + 16 * i][tx] = best[i];
        sidx[ty + 16 * i][tx]  = bidx[i];
    }
    __syncthreads();

    if (tid < MT) {
        float bb = sbest[tid][0];
        int   bi = sidx[tid][0];
        #pragma unroll
        for (int t = 1; t < 16; t++) {
            float v  = sbest[tid][t];
            int   id = sidx[tid][t];
            if (v > bb || (v == bb && id < bi)) { bb = v; bi = id; }
        }
        swin[tid] = bi;
        atomicAdd(&d_counts[bi], 1u);
    }
    __syncthreads();

    // segment-sum: each of 256 threads adds one dim of each winning row
    for (int r = 0; r < MT; ++r) {
        int gw = swin[r];
        atomicAdd(&d_sums[gw * D + tid], x[(bm + r) * D + tid]);
    }
}

// ---------------------------------------------------------------------------
// K2: out = beta*g + (1-beta) * sums / max(count, 1)
// ---------------------------------------------------------------------------
__global__ void __launch_bounds__(256) finalize_kernel(const float* __restrict__ gf,
                                                       float* __restrict__ out) {
    int i = blockIdx.x * 256 + threadIdx.x;
    int g = i >> 8;
    unsigned int c = d_counts[g];
    float cnt = (float)(c > 1u ? c : 1u);
    out[i] = 0.99f * gf[i] + 0.01f * (d_sums[i] / cnt);
}

// ---------------------------------------------------------------------------
extern "C" void kernel_launch(void* const* d_in, const int* in_sizes, int n_in,
                              void* d_out, int out_size) {
    const float* x;
    const float* gf;
    if (in_sizes[0] == B_ROWS * D) {          // defensive input-order resolve
        x  = (const float*)d_in[0];
        gf = (const float*)d_in[1];
    } else {
        x  = (const float*)d_in[1];
        gf = (const float*)d_in[0];
    }
    float* out = (float*)d_out;

    prep_kernel<<<N_G, 256>>>(gf);
    assign_kernel<<<B_ROWS / MT, 256>>>(x, gf);
    finalize_kernel<<<(N_G * D) / 256, 256>>>(gf, out);
}

// round 3
// speedup vs baseline: 5.5011x; 5.5011x over previous
#include <cuda_runtime.h>
#include <cuda_bf16.h>
#include <stdint.h>
#include <math.h>

#define B_ROWS 16384
#define N_G    8192
#define D      256
#define MT     128          // M rows per CTA
#define NTile  128          // N cols per tile
#define NTILES (N_G / NTile)        // 64
#define NCHUNK (NTILES * 8)         // 512 flattened 32-K chunks

#define A_STRIDE 260        // floats; 260 % 32 == 4 -> conflict-free frag loads
#define B_STRIDE 36         // floats; 36  % 32 == 4 -> conflict-free frag loads

#define SM_B       (MT * A_STRIDE * 4)            // 133120
#define B_BUF      (NTile * B_STRIDE * 4)         // 18432
#define SM_TOP     (SM_B + 2 * B_BUF)             // 169984
#define SM_WIN     (SM_TOP + 4096)
#define SMEM_TOTAL (SM_WIN + 512)                 // 174592 bytes

// ---------------- device scratch (no allocation allowed) ----------------
__device__ float        d_xt[B_ROWS * D];   // tf32-valued x
__device__ float        d_gt[N_G * D];      // tf32-valued normalized g
__device__ float        d_rnorm[N_G];
__device__ float        d_sums[N_G * D];
__device__ unsigned int d_counts[N_G];

// ---------------- helpers ----------------
__device__ __forceinline__ uint32_t smem_u32(const void* p) {
    uint32_t a;
    asm("{ .reg .u64 t; cvta.to.shared.u64 t, %1; cvt.u32.u64 %0, t; }" : "=r"(a) : "l"(p));
    return a;
}

__device__ __forceinline__ float to_tf32(float v) {
    uint32_t r;
    asm("cvt.rna.tf32.f32 %0, %1;" : "=r"(r) : "f"(v));
    return __uint_as_float(r);
}

__device__ __forceinline__ void mma_tf32(float c[4], const uint32_t a[4], const uint32_t b[2]) {
    asm volatile(
        "mma.sync.aligned.m16n8k8.row.col.f32.tf32.tf32.f32 "
        "{%0,%1,%2,%3}, {%4,%5,%6,%7}, {%8,%9}, {%0,%1,%2,%3};"
        : "+f"(c[0]), "+f"(c[1]), "+f"(c[2]), "+f"(c[3])
        : "r"(a[0]), "r"(a[1]), "r"(a[2]), "r"(a[3]), "r"(b[0]), "r"(b[1]));
}

// merge top-2 pair (b2,i2,s2,j2) into (b1,i1,s1,j1); ties -> smaller index
__device__ __forceinline__ void top2_merge(float& b1, int& i1, float& s1, int& j1,
                                           float b2, int i2, float s2, int j2) {
    if (b2 > b1 || (b2 == b1 && i2 < i1)) {
        float cs; int cj;
        if (b1 > s2 || (b1 == s2 && i1 < j2)) { cs = b1; cj = i1; } else { cs = s2; cj = j2; }
        b1 = b2; i1 = i2; s1 = cs; j1 = cj;
    } else if (b2 > s1 || (b2 == s1 && i2 < j1)) {
        s1 = b2; j1 = i2;
    }
}

// ---------------------------------------------------------------------------
// prep: x -> tf32
// ---------------------------------------------------------------------------
__global__ void __launch_bounds__(256) conv_x_kernel(const float* __restrict__ x) {
    int i = blockIdx.x * 256 + threadIdx.x;
    d_xt[i] = to_tf32(x[i]);
}

// ---------------------------------------------------------------------------
// prep: normalize g, convert to tf32; zero sums/counts; keep rnorm
// ---------------------------------------------------------------------------
__global__ void __launch_bounds__(256) prep_g_kernel(const float* __restrict__ gf) {
    int g = blockIdx.x;
    int t = threadIdx.x;
    float v = gf[g * D + t];
    d_sums[g * D + t] = 0.0f;

    float s = v * v;
    #pragma unroll
    for (int o = 16; o; o >>= 1) s += __shfl_xor_sync(0xFFFFFFFFu, s, o);
    __shared__ float red[8];
    __shared__ float srn;
    if ((t & 31) == 0) red[t >> 5] = s;
    __syncthreads();
    if (t < 8) {
        float r = red[t];
        #pragma unroll
        for (int o = 4; o; o >>= 1) r += __shfl_xor_sync(0xFFu, r, o);
        if (t == 0) {
            float rn = 1.0f / fmaxf(sqrtf(r), 1e-12f);
            srn = rn;
            d_rnorm[g] = rn;
            d_counts[g] = 0u;
        }
    }
    __syncthreads();
    d_gt[g * D + t] = to_tf32(v * srn);
}

// ---------------------------------------------------------------------------
// main: tf32 mma.sync GEMM + fused top-2 argmax + repair + segment-sum
//   grid = 128 CTAs, 256 threads = 8 warps in 4(M) x 2(N) layout
// ---------------------------------------------------------------------------
__global__ void __launch_bounds__(256, 1)
assign_kernel(const float* __restrict__ x, const float* __restrict__ gf) {
    extern __shared__ char smem[];
    float* As    = (float*)smem;                   // [128][260]
    float* Bs    = (float*)(smem + SM_B);          // [2][128][36]
    float* tb_s  = (float*)(smem + SM_TOP);        // [256]
    float* ts_s  = tb_s + 256;
    int*   tbi_s = (int*)(ts_s + 256);
    int*   tsi_s = tbi_s + 256;
    int*   swin  = (int*)(smem + SM_WIN);

    const int tid  = threadIdx.x;
    const int wid  = tid >> 5;
    const int lane = tid & 31;
    const int wm   = wid >> 1;          // 0..3
    const int wn   = wid & 1;           // 0..1
    const int l4   = lane >> 2;         // 0..7
    const int lq   = lane & 3;          // 0..3
    const int bm   = blockIdx.x * MT;

    // ---- load A (tf32 x rows) into SMEM once ----
    for (int i = tid; i < MT * 64; i += 256) {
        int m = i >> 6, cq = (i & 63) << 2;
        float4 v = *(const float4*)&d_xt[(size_t)(bm + m) * D + cq];
        *(float4*)&As[m * A_STRIDE + cq] = v;
    }
    __syncthreads();

    // ---- B chunk prefetch: chunk t = (tile = t>>3, kc = t&7) -> buf t&1 ----
    const int nrow = tid >> 1;          // 0..127
    const int half = tid & 1;           // 0..1
    auto prefetchB = [&](int t) {
        int tile = t >> 3, kc = t & 7;
        const float* src = &d_gt[(size_t)(tile * NTile + nrow) * D + kc * 32 + half * 16];
        uint32_t dst = smem_u32(&Bs[(t & 1) * NTile * B_STRIDE + nrow * B_STRIDE + half * 16]);
        #pragma unroll
        for (int q = 0; q < 4; q++)
            asm volatile("cp.async.cg.shared.global [%0], [%1], 16;"
                         :: "r"(dst + q * 16), "l"(src + q * 4));
    };

    prefetchB(0);
    asm volatile("cp.async.commit_group;");

    float C[2][8][4];
    float tb[2][2], ts[2][2];
    int   tbi[2][2], tsi[2][2];
    #pragma unroll
    for (int mt = 0; mt < 2; mt++)
        #pragma unroll
        for (int h = 0; h < 2; h++) {
            tb[mt][h] = -1e30f; ts[mt][h] = -1e30f;
            tbi[mt][h] = 0;     tsi[mt][h] = 1;
        }

    for (int t = 0; t < NCHUNK; ++t) {
        const int tile = t >> 3, kc = t & 7;

        if (t + 1 < NCHUNK) prefetchB(t + 1);
        asm volatile("cp.async.commit_group;");
        asm volatile("cp.async.wait_group 1;");
        __syncthreads();

        if (kc == 0) {
            #pragma unroll
            for (int mt = 0; mt < 2; mt++)
                #pragma unroll
                for (int nt = 0; nt < 8; nt++)
                    #pragma unroll
                    for (int r = 0; r < 4; r++) C[mt][nt][r] = 0.0f;
        }

        const float* Bbuf = &Bs[(t & 1) * NTile * B_STRIDE];

        #pragma unroll
        for (int s = 0; s < 4; s++) {
            const int ccol = kc * 32 + s * 8 + lq;
            uint32_t a[2][4];
            #pragma unroll
            for (int mt = 0; mt < 2; mt++) {
                int r = wm * 32 + mt * 16 + l4;
                a[mt][0] = __float_as_uint(As[r * A_STRIDE + ccol]);
                a[mt][1] = __float_as_uint(As[(r + 8) * A_STRIDE + ccol]);
                a[mt][2] = __float_as_uint(As[r * A_STRIDE + ccol + 4]);
                a[mt][3] = __float_as_uint(As[(r + 8) * A_STRIDE + ccol + 4]);
            }
            uint32_t b[8][2];
            const int kk = s * 8 + lq;
            #pragma unroll
            for (int nt = 0; nt < 8; nt++) {
                int n = wn * 64 + nt * 8 + l4;
                b[nt][0] = __float_as_uint(Bbuf[n * B_STRIDE + kk]);
                b[nt][1] = __float_as_uint(Bbuf[n * B_STRIDE + kk + 4]);
            }
            #pragma unroll
            for (int mt = 0; mt < 2; mt++)
                #pragma unroll
                for (int nt = 0; nt < 8; nt++)
                    mma_tf32(C[mt][nt], a[mt], b[nt]);
        }
        __syncthreads();    // protect buf t&1 before it is refilled at t+1

        if (kc == 7) {
            // register-only top-2 update (cols ascending within each lane/row)
            const int bn = tile * NTile;
            #pragma unroll
            for (int nt = 0; nt < 8; nt++) {
                const int n0 = bn + wn * 64 + nt * 8 + 2 * lq;
                #pragma unroll
                for (int mt = 0; mt < 2; mt++)
                    #pragma unroll
                    for (int h = 0; h < 2; h++) {
                        float v0 = C[mt][nt][2 * h];
                        float v1 = C[mt][nt][2 * h + 1];
                        if (v0 > tb[mt][h]) { ts[mt][h] = tb[mt][h]; tsi[mt][h] = tbi[mt][h];
                                              tb[mt][h] = v0; tbi[mt][h] = n0; }
                        else if (v0 > ts[mt][h]) { ts[mt][h] = v0; tsi[mt][h] = n0; }
                        if (v1 > tb[mt][h]) { ts[mt][h] = tb[mt][h]; tsi[mt][h] = tbi[mt][h];
                                              tb[mt][h] = v1; tbi[mt][h] = n0 + 1; }
                        else if (v1 > ts[mt][h]) { ts[mt][h] = v1; tsi[mt][h] = n0 + 1; }
                    }
            }
        }
    }

    // ---- cross-lane top-2 reduction within each quad (same row) ----
    #pragma unroll
    for (int mt = 0; mt < 2; mt++)
        #pragma unroll
        for (int h = 0; h < 2; h++) {
            float b = tb[mt][h], s = ts[mt][h];
            int   bi = tbi[mt][h], si = tsi[mt][h];
            #pragma unroll
            for (int off = 1; off <= 2; off <<= 1) {
                float ob  = __shfl_xor_sync(0xFFFFFFFFu, b, off);
                float os  = __shfl_xor_sync(0xFFFFFFFFu, s, off);
                int   obi = __shfl_xor_sync(0xFFFFFFFFu, bi, off);
                int   osi = __shfl_xor_sync(0xFFFFFFFFu, si, off);
                top2_merge(b, bi, s, si, ob, obi, os, osi);
            }
            if (lq == 0) {
                int row = wm * 32 + mt * 16 + h * 8 + l4;
                int idx = row * 2 + wn;
                tb_s[idx] = b; ts_s[idx] = s; tbi_s[idx] = bi; tsi_s[idx] = si;
            }
        }
    __syncthreads();

    // ---- per-row final merge + exact fp32 repair + winner ----
    if (tid < MT) {
        float b = tb_s[tid * 2], s = ts_s[tid * 2];
        int   bi = tbi_s[tid * 2], si = tsi_s[tid * 2];
        top2_merge(b, bi, s, si, tb_s[tid * 2 + 1], tbi_s[tid * 2 + 1],
                   ts_s[tid * 2 + 1], tsi_s[tid * 2 + 1]);

        if (b - s < 3e-2f) {      // tf32 error tail ~2e-3 on this logit scale
            const float* xr = x  + (size_t)(bm + tid) * D;
            const float* ga = gf + (size_t)bi * D;
            const float* gb = gf + (size_t)si * D;
            float va = 0.0f, vb = 0.0f;
            #pragma unroll 8
            for (int k = 0; k < D; k++) {
                float xv = xr[k];
                va = fmaf(xv, ga[k], va);
                vb = fmaf(xv, gb[k], vb);
            }
            va *= d_rnorm[bi];
            vb *= d_rnorm[si];
            if (vb > va || (vb == va && si < bi)) bi = si;
        }
        swin[tid] = bi;
        atomicAdd(&d_counts[bi], 1u);
    }
    __syncthreads();

    // ---- segment-sum: threads 0..255 each own one dim, loop 128 rows ----
    for (int r = 0; r < MT; r++) {
        int g = swin[r];
        atomicAdd(&d_sums[(size_t)g * D + tid], x[(size_t)(bm + r) * D + tid]);
    }
}

// ---------------------------------------------------------------------------
// finalize: out = 0.99*g + 0.01 * sums / max(count,1)
// ---------------------------------------------------------------------------
__global__ void __launch_bounds__(256) finalize_kernel(const float* __restrict__ gf,
                                                       float* __restrict__ out) {
    int i = blockIdx.x * 256 + threadIdx.x;
    int g = i >> 8;
    unsigned int c = d_counts[g];
    float cnt = (float)(c > 1u ? c : 1u);
    out[i] = 0.99f * gf[i] + 0.01f * (d_sums[i] / cnt);
}

// ---------------------------------------------------------------------------
extern "C" void kernel_launch(void* const* d_in, const int* in_sizes, int n_in,
                              void* d_out, int out_size) {
    const float* x;
    const float* gf;
    if (in_sizes[0] == B_ROWS * D) {
        x  = (const float*)d_in[0];
        gf = (const float*)d_in[1];
    } else {
        x  = (const float*)d_in[1];
        gf = (const float*)d_in[0];
    }
    float* out = (float*)d_out;

    cudaFuncSetAttribute(assign_kernel, cudaFuncAttributeMaxDynamicSharedMemorySize, SMEM_TOTAL);

    conv_x_kernel<<<(B_ROWS * D) / 256, 256>>>(x);
    prep_g_kernel<<<N_G, 256>>>(gf);
    assign_kernel<<<B_ROWS / MT, 256, SMEM_TOTAL>>>(x, gf);
    finalize_kernel<<<(N_G * D) / 256, 256>>>(gf, out);
}